// round 1
// baseline (speedup 1.0000x reference)
#include <cuda_runtime.h>
#include <math.h>

// Problem constants
#define DIN   256      // agent input dim
#define C6    192      // S*6 = 32*6
#define CAN   128      // canvas size
#define NT    50       // samples per curve
#define NPTS  (32*NT)  // 1600 curve points per image
#define HDIM  129      // center coords are in [0,128]
#define HSIZE (HDIM*HDIM)

// ---------------------------------------------------------------------------
// Kernel A: mu = x@W + b ; sample = sigmoid(mu); constant log_prob / entropy.
// Block handles 16 batch rows with 192 threads (one thread per output col).
// x tile is staged in shared transposed (stride 20 floats -> float4-aligned,
// conflict-light) so the inner loop is 4x LDS.128 + 16 FFMA + 1 LDG per k.
// ---------------------------------------------------------------------------
#define ROWS_PER_BLK 16
#define XS_STRIDE 20

__global__ void __launch_bounds__(C6) agent_kernel(
    const float* __restrict__ x,
    const float* __restrict__ W,
    const float* __restrict__ bvec,
    float* __restrict__ out,   // full output buffer
    int B)
{
    __shared__ float xs[DIN * XS_STRIDE];  // [k][r], r in 0..15 (+pad)

    const int j    = threadIdx.x;          // output column 0..191
    const int row0 = blockIdx.x * ROWS_PER_BLK;

    // Stage x tile (16 rows x 256 cols), transposed into shared.
    for (int idx = j; idx < ROWS_PER_BLK * DIN; idx += C6) {
        int r = idx >> 8;        // idx / 256
        int k = idx & 255;       // idx % 256
        xs[k * XS_STRIDE + r] = x[(size_t)(row0 + r) * DIN + k];
    }
    __syncthreads();

    float acc[ROWS_PER_BLK];
    {
        float bj = bvec[j];
#pragma unroll
        for (int r = 0; r < ROWS_PER_BLK; ++r) acc[r] = bj;
    }

    const float* Wj = W + j;
#pragma unroll 4
    for (int k = 0; k < DIN; ++k) {
        float w = __ldg(&Wj[(size_t)k * C6]);
        const float4* a4 = (const float4*)&xs[k * XS_STRIDE];
        float4 a0 = a4[0], a1 = a4[1], a2 = a4[2], a3 = a4[3];
        acc[0]  = fmaf(a0.x, w, acc[0]);
        acc[1]  = fmaf(a0.y, w, acc[1]);
        acc[2]  = fmaf(a0.z, w, acc[2]);
        acc[3]  = fmaf(a0.w, w, acc[3]);
        acc[4]  = fmaf(a1.x, w, acc[4]);
        acc[5]  = fmaf(a1.y, w, acc[5]);
        acc[6]  = fmaf(a1.z, w, acc[6]);
        acc[7]  = fmaf(a1.w, w, acc[7]);
        acc[8]  = fmaf(a2.x, w, acc[8]);
        acc[9]  = fmaf(a2.y, w, acc[9]);
        acc[10] = fmaf(a2.z, w, acc[10]);
        acc[11] = fmaf(a2.w, w, acc[11]);
        acc[12] = fmaf(a3.x, w, acc[12]);
        acc[13] = fmaf(a3.y, w, acc[13]);
        acc[14] = fmaf(a3.z, w, acc[14]);
        acc[15] = fmaf(a3.w, w, acc[15]);
    }

    // Output layout: [sketch B*128*128][log_prob B][entropy B][sample B*192]
    const size_t off_lp  = (size_t)B * (CAN * CAN);
    const size_t off_ent = off_lp + B;
    const size_t off_smp = off_ent + B;

    // log_prob / entropy are constants (raw == mu).
    const float logscale = logf(1e-4f);
    const float l2pi     = logf(6.2831855f);           // log(fl32(2*pi))
    const float lp  = 192.0f * (-logscale - 0.5f * l2pi);
    const float ent = 192.0f * (0.5f + 0.5f * l2pi + logscale);
    if (j < ROWS_PER_BLK) {
        out[off_lp  + row0 + j] = lp;
        out[off_ent + row0 + j] = ent;
    }

    float* smp = out + off_smp;
#pragma unroll
    for (int r = 0; r < ROWS_PER_BLK; ++r) {
        float m = acc[r];
        float s = 1.0f / (1.0f + expf(-m));
        smp[(size_t)(row0 + r) * C6 + j] = s;
    }
}

// ---------------------------------------------------------------------------
// Kernel B: paint. One block per batch image.
//  1) histogram rounded bezier centers into shared H[129][129] (atomicAdd)
//  2) reconstruct canvas via 3x3 weighted stencil (separable clipping weights)
// ---------------------------------------------------------------------------
__global__ void __launch_bounds__(256) paint_kernel(
    const float* __restrict__ sample,   // [B, 192]
    float* __restrict__ sketch)         // [B, 128, 128]
{
    extern __shared__ unsigned int H[];   // HSIZE counts
    __shared__ float prm[C6];

    const int b   = blockIdx.x;
    const int tid = threadIdx.x;

    for (int i = tid; i < HSIZE; i += 256) H[i] = 0u;
    if (tid < C6) prm[tid] = __fmul_rn(sample[(size_t)b * C6 + tid], 128.0f);
    __syncthreads();

    const float dt = 1.0f / 49.0f;   // fl32((1-0)/(NT-1))
    for (int p = tid; p < NPTS; p += 256) {
        int s = p / NT;
        int i = p - s * NT;
        float t = (i == NT - 1) ? 1.0f : __fmul_rn((float)i, dt);
        float u = __fadd_rn(1.0f, -t);
        float uu  = __fmul_rn(u, u);
        float ut2 = __fmul_rn(__fmul_rn(2.0f, u), t);
        float tt  = __fmul_rn(t, t);
        const float* q = &prm[s * 6];
        float X = __fadd_rn(__fadd_rn(__fmul_rn(uu, q[0]), __fmul_rn(ut2, q[2])),
                            __fmul_rn(tt, q[4]));
        float Y = __fadd_rn(__fadd_rn(__fmul_rn(uu, q[1]), __fmul_rn(ut2, q[3])),
                            __fmul_rn(tt, q[5]));
        int cx = (int)rintf(X);
        int cy = (int)rintf(Y);
        cx = min(max(cx, 0), HDIM - 1);
        cy = min(max(cy, 0), HDIM - 1);
        atomicAdd(&H[cx * HDIM + cy], 1u);
    }
    __syncthreads();

    float* dst = sketch + (size_t)b * (CAN * CAN);
    for (int idx = tid; idx < CAN * CAN; idx += 256) {
        int px = idx >> 7;
        int py = idx & 127;

        // x taps: centers contributing to this pixel via clip(cx+dx)==px
        int x0, x1, x2; unsigned int wx0, wx1, wx2;
        if (px == 0)            { x0 = 0;   x1 = 0;   x2 = 1;   wx0 = 0; wx1 = 2; wx2 = 1; }
        else if (px == CAN - 1) { x0 = 126; x1 = 127; x2 = 128; wx0 = 1; wx1 = 2; wx2 = 3; }
        else                    { x0 = px-1; x1 = px;  x2 = px+1; wx0 = 1; wx1 = 1; wx2 = 1; }

        int y0, y1, y2; unsigned int wy0, wy1, wy2;
        if (py == 0)            { y0 = 0;   y1 = 0;   y2 = 1;   wy0 = 0; wy1 = 2; wy2 = 1; }
        else if (py == CAN - 1) { y0 = 126; y1 = 127; y2 = 128; wy0 = 1; wy1 = 2; wy2 = 3; }
        else                    { y0 = py-1; y1 = py;  y2 = py+1; wy0 = 1; wy1 = 1; wy2 = 1; }

        const unsigned int* r0 = &H[x0 * HDIM];
        const unsigned int* r1 = &H[x1 * HDIM];
        const unsigned int* r2 = &H[x2 * HDIM];

        unsigned int n =
            wx0 * (wy0 * r0[y0] + wy1 * r0[y1] + wy2 * r0[y2]) +
            wx1 * (wy0 * r1[y0] + wy1 * r1[y1] + wy2 * r1[y2]) +
            wx2 * (wy0 * r2[y0] + wy1 * r2[y1] + wy2 * r2[y2]);

        float v = __fadd_rn(0.3f, __fmul_rn((float)n, -0.07f));
        v = fminf(1.0f, fmaxf(0.0f, v));
        dst[idx] = v;
    }
}

// ---------------------------------------------------------------------------
extern "C" void kernel_launch(void* const* d_in, const int* in_sizes, int n_in,
                              void* d_out, int out_size)
{
    const float* x    = (const float*)d_in[0];
    const float* W    = (const float*)d_in[1];
    const float* bv   = (const float*)d_in[2];
    float* out        = (float*)d_out;

    int B = in_sizes[0] / DIN;   // 2048

    // 66.5 KB dynamic shared for the 129x129 histogram.
    cudaFuncSetAttribute(paint_kernel,
                         cudaFuncAttributeMaxDynamicSharedMemorySize,
                         HSIZE * (int)sizeof(unsigned int));

    agent_kernel<<<B / ROWS_PER_BLK, C6>>>(x, W, bv, out, B);

    const float* sample = out + (size_t)B * (CAN * CAN) + 2 * (size_t)B;
    paint_kernel<<<B, 256, HSIZE * sizeof(unsigned int)>>>(sample, out);
}

// round 3
// speedup vs baseline: 1.9938x; 1.9938x over previous
#include <cuda_runtime.h>
#include <math.h>

// Problem constants
#define DIN   256      // agent input dim
#define C6    192      // S*6 = 32*6
#define CAN   128      // canvas size
#define NT    50       // samples per curve
#define NPTS  (32*NT)  // 1600 curve points per image
#define HDIM  129      // center coords are in [0,128]
#define HROW  65       // u32 words per H row (129 u16 cy slots + 1 pad, packed pairs)
#define HPWORDS (HDIM*HROW)   // 8385
#define GY_OFF  8388          // Gy base, padded to 16B boundary (8385 -> 8388)
#define GROW  64       // u32 words per Gy row (128 py slots packed)
#define GWORDS  (HDIM*GROW)   // 8256
#define SMEM_PAINT ((GY_OFF + GWORDS) * 4)   // 66576 B

// ---------------------------------------------------------------------------
// Kernel A: mu = x@W + b ; sample = sigmoid(mu); constant log_prob / entropy.
// 4 batch rows per block, 192 threads (one per output col), 512 blocks.
// xs[k] is a broadcast float4 (rows 0..3 of col k): 1 LDS.128 + 4 FFMA + 1 LDG
// per k-step.
// ---------------------------------------------------------------------------
#define RPB 4

__global__ void __launch_bounds__(C6) agent_kernel(
    const float* __restrict__ x,
    const float* __restrict__ W,
    const float* __restrict__ bvec,
    float* __restrict__ out,   // full output buffer
    int B)
{
    __shared__ float xs[DIN * RPB];   // [k][r]

    const int j    = threadIdx.x;          // output column 0..191
    const int row0 = blockIdx.x * RPB;

    for (int idx = j; idx < RPB * DIN; idx += C6) {
        int r = idx >> 8;        // idx / 256
        int k = idx & 255;       // idx % 256
        xs[k * RPB + r] = x[(size_t)(row0 + r) * DIN + k];
    }
    __syncthreads();

    float bj = bvec[j];
    float a0 = bj, a1 = bj, a2 = bj, a3 = bj;

    const float* Wj = W + j;
#pragma unroll 8
    for (int k = 0; k < DIN; ++k) {
        float w = __ldg(&Wj[(size_t)k * C6]);
        float4 v = *(const float4*)&xs[k * RPB];   // broadcast
        a0 = fmaf(v.x, w, a0);
        a1 = fmaf(v.y, w, a1);
        a2 = fmaf(v.z, w, a2);
        a3 = fmaf(v.w, w, a3);
    }

    // Output layout: [sketch B*128*128][log_prob B][entropy B][sample B*192]
    const size_t off_lp  = (size_t)B * (CAN * CAN);
    const size_t off_ent = off_lp + B;
    const size_t off_smp = off_ent + B;

    // log_prob / entropy are constants (raw == mu).
    const float logscale = logf(1e-4f);
    const float l2pi     = logf(6.2831855f);           // log(fl32(2*pi))
    const float lp  = 192.0f * (-logscale - 0.5f * l2pi);
    const float ent = 192.0f * (0.5f + 0.5f * l2pi + logscale);
    if (j < RPB) {
        out[off_lp  + row0 + j] = lp;
        out[off_ent + row0 + j] = ent;
    }

    float* smp = out + off_smp + (size_t)row0 * C6 + j;
    smp[0 * C6] = 1.0f / (1.0f + expf(-a0));
    smp[1 * C6] = 1.0f / (1.0f + expf(-a1));
    smp[2 * C6] = 1.0f / (1.0f + expf(-a2));
    smp[3 * C6] = 1.0f / (1.0f + expf(-a3));
}

// ---------------------------------------------------------------------------
// Kernel B: paint. One block per batch image.
//  1) histogram rounded bezier centers into packed-u16 Hp[129][65 u32]
//  2) pass A (y-window): Gy[cx][py] packed u16, via funnel shifts
//  3) pass B (x-window): n(px,py), LUT lookup (clip saturates at n=5), STG.128
// Edge weights from clipping:  p=0 -> {2,1} on centers {0,1};
//                              p=127 -> {1,2,3} on centers {126,127,128}.
// All packed-u16 sums bounded by 14400 < 65536: no carry across halves.
// ---------------------------------------------------------------------------
__global__ void __launch_bounds__(256) paint_kernel(
    const float* __restrict__ sample,   // [B, 192]
    float* __restrict__ sketch)         // [B, 128, 128]
{
    extern __shared__ uint4 sh16[];       // force 16B alignment
    unsigned int* sh = (unsigned int*)sh16;
    unsigned int* Hp = sh;              // [129][65] u32 (u16 pairs along cy)
    unsigned int* Gy = sh + GY_OFF;     // [129][64] u32 (u16 pairs along py), 16B-aligned
    __shared__ float prm[C6];
    __shared__ float lut[8];

    const int b   = blockIdx.x;
    const int tid = threadIdx.x;

    for (int i = tid; i < HPWORDS; i += 256) Hp[i] = 0u;
    if (tid < C6) prm[tid] = __fmul_rn(sample[(size_t)b * C6 + tid], 128.0f);
    if (tid < 8) {
        float v = __fadd_rn(0.3f, __fmul_rn((float)tid, -0.07f));
        lut[tid] = fmaxf(v, 0.0f);     // saturates to 0 for n>=5
    }
    __syncthreads();

    // ---- histogram of rounded curve centers ----
    const float dt = 1.0f / 49.0f;   // fl32((1-0)/(NT-1))
    for (int p = tid; p < NPTS; p += 256) {
        int s = p / NT;
        int i = p - s * NT;
        float t = (i == NT - 1) ? 1.0f : __fmul_rn((float)i, dt);
        float u = __fadd_rn(1.0f, -t);
        float uu  = __fmul_rn(u, u);
        float ut2 = __fmul_rn(__fmul_rn(2.0f, u), t);
        float tt  = __fmul_rn(t, t);
        const float* q = &prm[s * 6];
        float X = __fadd_rn(__fadd_rn(__fmul_rn(uu, q[0]), __fmul_rn(ut2, q[2])),
                            __fmul_rn(tt, q[4]));
        float Y = __fadd_rn(__fadd_rn(__fmul_rn(uu, q[1]), __fmul_rn(ut2, q[3])),
                            __fmul_rn(tt, q[5]));
        int cx = (int)rintf(X);
        int cy = (int)rintf(Y);
        cx = min(max(cx, 0), HDIM - 1);
        cy = min(max(cy, 0), HDIM - 1);
        atomicAdd(&Hp[cx * HROW + (cy >> 1)], 1u << ((cy & 1) * 16));
    }
    __syncthreads();

    // ---- pass A: y-window sums -> Gy (packed u16 pairs of py) ----
    for (int e = tid; e < GWORDS; e += 256) {
        int row = e >> 6;           // cx
        int i   = e & 63;           // py pair index
        const unsigned int* hr = Hp + row * HROW;
        unsigned int p0 = hr[i];
        unsigned int pm = (i == 0) ? (p0 << 16) : hr[i - 1]; // makes py=0 = 2H0+H1
        unsigned int pp = hr[i + 1];                         // i=63 -> word 64 (h128|0)
        unsigned int a  = __funnelshift_l(pm, p0, 16);       // (h[2i-1], h[2i])
        unsigned int c  = __funnelshift_l(p0, pp, 16);       // (h[2i+1], h[2i+2])
        unsigned int o  = a + p0 + c;
        if (i == 63) {
            // py=127 needs H126 + 2*H127 + 3*H128; a+b+c gave H126+H127+H128
            unsigned int h127 = p0 >> 16;
            unsigned int h128 = pp & 0xffffu;
            o += (h127 + 2u * h128) << 16;
        }
        Gy[e] = o;
    }
    __syncthreads();

    // ---- pass B: x-window + LUT + vectorized store ----
    float* dst = sketch + (size_t)b * (CAN * CAN);
    for (int cch = tid; cch < 2048; cch += 256) {   // 128 px * 16 chunks
        int px = cch >> 4;
        int j0 = (cch & 15) << 2;                   // u32 offset within row

        uint4 n4;
        if (px == 0) {
            uint4 g0 = *(const uint4*)&Gy[0 * GROW + j0];
            uint4 g1 = *(const uint4*)&Gy[1 * GROW + j0];
            n4.x = 2u * g0.x + g1.x;  n4.y = 2u * g0.y + g1.y;
            n4.z = 2u * g0.z + g1.z;  n4.w = 2u * g0.w + g1.w;
        } else if (px == CAN - 1) {
            uint4 ga = *(const uint4*)&Gy[126 * GROW + j0];
            uint4 gb = *(const uint4*)&Gy[127 * GROW + j0];
            uint4 gc = *(const uint4*)&Gy[128 * GROW + j0];
            n4.x = ga.x + 2u * gb.x + 3u * gc.x;
            n4.y = ga.y + 2u * gb.y + 3u * gc.y;
            n4.z = ga.z + 2u * gb.z + 3u * gc.z;
            n4.w = ga.w + 2u * gb.w + 3u * gc.w;
        } else {
            uint4 ga = *(const uint4*)&Gy[(px - 1) * GROW + j0];
            uint4 gb = *(const uint4*)&Gy[(px    ) * GROW + j0];
            uint4 gc = *(const uint4*)&Gy[(px + 1) * GROW + j0];
            n4.x = ga.x + gb.x + gc.x;
            n4.y = ga.y + gb.y + gc.y;
            n4.z = ga.z + gb.z + gc.z;
            n4.w = ga.w + gb.w + gc.w;
        }

        float4 o0, o1;
        o0.x = lut[min(n4.x & 0xffffu, 5u)];
        o0.y = lut[min(n4.x >> 16,     5u)];
        o0.z = lut[min(n4.y & 0xffffu, 5u)];
        o0.w = lut[min(n4.y >> 16,     5u)];
        o1.x = lut[min(n4.z & 0xffffu, 5u)];
        o1.y = lut[min(n4.z >> 16,     5u)];
        o1.z = lut[min(n4.w & 0xffffu, 5u)];
        o1.w = lut[min(n4.w >> 16,     5u)];

        float* d = dst + px * CAN + (j0 << 1);
        ((float4*)d)[0] = o0;
        ((float4*)d)[1] = o1;
    }
}

// ---------------------------------------------------------------------------
extern "C" void kernel_launch(void* const* d_in, const int* in_sizes, int n_in,
                              void* d_out, int out_size)
{
    const float* x    = (const float*)d_in[0];
    const float* W    = (const float*)d_in[1];
    const float* bv   = (const float*)d_in[2];
    float* out        = (float*)d_out;

    int B = in_sizes[0] / DIN;   // 2048

    cudaFuncSetAttribute(paint_kernel,
                         cudaFuncAttributeMaxDynamicSharedMemorySize,
                         SMEM_PAINT);

    agent_kernel<<<B / RPB, C6>>>(x, W, bv, out, B);

    const float* sample = out + (size_t)B * (CAN * CAN) + 2 * (size_t)B;
    paint_kernel<<<B, 256, SMEM_PAINT>>>(sample, out);
}